// round 14
// baseline (speedup 1.0000x reference)
#include <cuda_runtime.h>
#include <cuda_bf16.h>
#include <cstdint>

#define NN 2048
#define NROWS 16384
#define RC 2                 // rows in flight per block
#define ITER 8               // row-sets per block
#define THREADS 256          // 8 warps: 4 warps per row, 2 rows
#define CHUNK 16
// padded layout: p(k) = k + (k>>5); row stride = 2048 + 64 = 2112 words
#define PADSTRIDE 2112
#define PTOP 2110            // p(2047)

__device__ float g_cs[NN];
__device__ float g_sn[NN];

__global__ void rg_sincos_kernel(const float* __restrict__ angles) {
    int k = blockIdx.x * blockDim.x + threadIdx.x;
    if (k < NN) {
        float s, c;
        sincosf(angles[k], &s, &c);
        g_cs[k] = c;
        g_sn[k] = s;
    }
}

// Persistent: 8 row-sets/block, double-buffered LDG->reg->STS staging,
// cos/sin chunk tables in registers (loaded once per block),
// 4 warps/row chunk-16 affine scan, x re-read from smem (no xv cache).
__global__ __launch_bounds__(THREADS, 4)
void rg_givens_kernel(const float* __restrict__ x, float* __restrict__ y) {
    extern __shared__ float sm[];
    float* bufs = sm;                                  // [2][RC][PADSTRIDE]
    float* c_s  = sm + 2 * RC * PADSTRIDE;             // [PADSTRIDE]
    float* s_s  = c_s + PADSTRIDE;                     // [PADSTRIDE]
    float* wmA  = s_s + PADSTRIDE;                     // [RC][4]
    float* wmB  = wmA + RC * 4;                        // [RC][4]

    const int tid  = threadIdx.x;
    const int lane = tid & 31;
    const int w    = tid >> 5;
    const int rib  = w >> 2;          // row in set (0..1)
    const int h    = w & 3;           // quarter of row
    const long base = (long)blockIdx.x * (RC * ITER);

    const int C = h * 32 + lane;                 // chunk id 0..127 (fixed per thread)
    const int pbase = 16 * C + (C >> 1);
    const int pnext = 16 * (C + 1) + ((C + 1) >> 1);

    // ---- one-time: tables into padded smem ----
    #pragma unroll
    for (int k = tid; k < NN; k += THREADS) {
        int p = k + (k >> 5);
        c_s[p] = g_cs[k];
        s_s[p] = g_sn[k];
    }

    // ---- prologue: stage row-set 0 into buf0; prime pf with set 1 ----
    float4 pf0, pf1, pf2, pf3;
    {
        const float* src = x + (base + rib) * NN;
        float* db = bufs + rib * PADSTRIDE;
        #pragma unroll
        for (int i = 0; i < 4; i++) {
            int v4 = h * 128 + i * 32 + lane;
            float4 val = *(const float4*)(src + v4 * 4);
            int k = v4 * 4;
            int p = k + (k >> 5);
            db[p + 0] = val.x; db[p + 1] = val.y;
            db[p + 2] = val.z; db[p + 3] = val.w;
        }
        const float* s1 = x + (base + RC + rib) * NN;
        pf0 = *(const float4*)(s1 + (h * 128 +  0 + lane) * 4);
        pf1 = *(const float4*)(s1 + (h * 128 + 32 + lane) * 4);
        pf2 = *(const float4*)(s1 + (h * 128 + 64 + lane) * 4);
        pf3 = *(const float4*)(s1 + (h * 128 + 96 + lane) * 4);
    }
    __syncthreads();

    // ---- one-time: chunk tables into registers (conflict-free LDS) ----
    float rc[CHUNK], rs[CHUNK];
    #pragma unroll
    for (int t = 0; t < CHUNK; t++) {
        rc[t] = c_s[pbase + t];
        rs[t] = s_s[pbase + t];
    }
    float Bm0 = 1.0f;
    #pragma unroll
    for (int t = 0; t < CHUNK; t++) Bm0 *= -rs[t];
    const float cT = c_s[PTOP];
    const float sT = s_s[PTOP];

    for (int it = 0; it < ITER; it++) {
        float* xr = bufs + (it & 1) * RC * PADSTRIDE + rib * PADSTRIDE;
        const long row = base + (long)it * RC + rib;

        const float x0 = xr[0];
        // boundary element (clobbered cross-lane in stage 3); C==0 gets w0
        float xlo;
        if (C == 0) {
            xlo = fmaf(sT, xr[PTOP], cT * x0);   // x~[0]
        } else {
            xlo = xr[pbase];
        }

        // ---- stage 2: chunk affine map (x from smem, tables from regs) ----
        float A = 0.0f;
        #pragma unroll
        for (int t = CHUNK - 1; t >= 1; t--) {
            A = fmaf(-rs[t], A, rc[t] * xr[pbase + t]);
        }
        A = fmaf(-rs[0], A, rc[0] * xlo);

        // ---- warp suffix scan ----
        float gA = A, gB = Bm0;
        #pragma unroll
        for (int d = 1; d < 32; d <<= 1) {
            float A2 = __shfl_down_sync(0xffffffffu, gA, d);
            float B2 = __shfl_down_sync(0xffffffffu, gB, d);
            if (lane + d < 32) {
                gA = fmaf(gB, A2, gA);
                gB = gB * B2;
            }
        }
        float nA = __shfl_down_sync(0xffffffffu, gA, 1);
        float nB = __shfl_down_sync(0xffffffffu, gB, 1);
        if (lane == 0) {
            wmA[rib * 4 + h] = gA;
            wmB[rib * 4 + h] = gB;
        }
        __syncthreads();   // barrier #1

        float cin = x0;
        #pragma unroll
        for (int j = 3; j >= 1; j--) {
            if (j > h) cin = fmaf(wmB[rib * 4 + j], cin, wmA[rib * 4 + j]);
        }
        float carry = (lane == 31) ? cin : fmaf(nB, cin, nA);

        // ---- stage 3: replay; re-read x, write y in place ----
        #pragma unroll
        for (int t = CHUNK - 1; t >= 1; t--) {
            float xv = xr[pbase + t];
            float out = fmaf(rc[t], carry, rs[t] * xv);
            carry = fmaf(-rs[t], carry, rc[t] * xv);
            if (t == CHUNK - 1) {
                if (C != 127) xr[pnext] = out;   // y[16(C+1)]
            } else {
                xr[pbase + t + 1] = out;         // y[16C+t+1]
            }
        }
        {
            float out = fmaf(rc[0], carry, rs[0] * xlo);
            carry = fmaf(-rs[0], carry, rc[0] * xlo);
            xr[pbase + 1] = out;                 // y[16C+1]
        }
        if (C == 0) xr[0] = carry;               // y[0]

        // ---- drain pf into the other buffer; issue LDG for set it+2 ----
        if (it + 1 < ITER) {
            float* db = bufs + ((it + 1) & 1) * RC * PADSTRIDE + rib * PADSTRIDE;
            #pragma unroll
            for (int i = 0; i < 4; i++) {
                float4 val = (i == 0) ? pf0 : (i == 1) ? pf1 : (i == 2) ? pf2 : pf3;
                int k = (h * 128 + i * 32 + lane) * 4;
                int p = k + (k >> 5);
                db[p + 0] = val.x; db[p + 1] = val.y;
                db[p + 2] = val.z; db[p + 3] = val.w;
            }
            if (it + 2 < ITER) {
                const float* sn = x + (base + (long)(it + 2) * RC + rib) * NN;
                pf0 = *(const float4*)(sn + (h * 128 +  0 + lane) * 4);
                pf1 = *(const float4*)(sn + (h * 128 + 32 + lane) * 4);
                pf2 = *(const float4*)(sn + (h * 128 + 64 + lane) * 4);
                pf3 = *(const float4*)(sn + (h * 128 + 96 + lane) * 4);
            }
        }
        __syncthreads();   // barrier #2: y complete, staging complete

        // ---- store y: padded smem -> coalesced float4 STG ----
        float* yrow = y + row * NN;
        #pragma unroll
        for (int i = 0; i < 4; i++) {
            int v4 = h * 128 + i * 32 + lane;
            int k = v4 * 4;
            int p = k + (k >> 5);
            float4 val;
            val.x = xr[p + 0];
            val.y = xr[p + 1];
            val.z = xr[p + 2];
            val.w = xr[p + 3];
            *(float4*)(yrow + v4 * 4) = val;
        }
    }
}

extern "C" void kernel_launch(void* const* d_in, const int* in_sizes, int n_in,
                              void* d_out, int out_size) {
    const float* x      = (const float*)d_in[0];   // [16384, 2048] fp32
    const float* angles = (const float*)d_in[1];   // [2048] fp32
    float* y = (float*)d_out;                      // [16384, 2048] fp32

    (void)in_sizes; (void)n_in; (void)out_size;

    rg_sincos_kernel<<<(NN + 255) / 256, 256>>>(angles);

    const int smem_bytes = (2 * RC * PADSTRIDE + 2 * PADSTRIDE + 2 * RC * 4) * sizeof(float);
    static bool attr_set = false;
    if (!attr_set) {
        cudaFuncSetAttribute(rg_givens_kernel,
                             cudaFuncAttributeMaxDynamicSharedMemorySize, smem_bytes);
        attr_set = true;
    }
    rg_givens_kernel<<<NROWS / (RC * ITER), THREADS, smem_bytes>>>(x, y);
}

// round 15
// speedup vs baseline: 1.1242x; 1.1242x over previous
#include <cuda_runtime.h>
#include <cuda_bf16.h>
#include <cstdint>

#define NN 2048
#define NROWS 16384
#define ROWS_PER_BLOCK 4
#define THREADS 512          // 16 warps: 4 warps per row
#define CHUNK 16
// padded layout: p(k) = k + (k>>5); row stride = 2048 + 64 = 2112 words
#define PADSTRIDE 2112
#define PTOP 2110            // p(2047)

__device__ float g_cs[NN];
__device__ float g_sn[NN];

__global__ void rg_sincos_kernel(const float* __restrict__ angles) {
    int k = blockIdx.x * blockDim.x + threadIdx.x;
    if (k < NN) {
        float s, c;
        sincosf(angles[k], &s, &c);
        g_cs[k] = c;
        g_sn[k] = s;
    }
}

// R3 champion structure + one-time register-resident cos/sin chunk tables.
// 4 warps/row, chunk-16 affine scan, xv register cache, padded smem staging.
__global__ __launch_bounds__(THREADS, 2)
void rg_givens_kernel(const float* __restrict__ x, float* __restrict__ y) {
    extern __shared__ float sm[];
    float* xs  = sm;                                   // [4][PADSTRIDE]
    float* c_s = sm + ROWS_PER_BLOCK * PADSTRIDE;      // [PADSTRIDE]
    float* s_s = c_s + PADSTRIDE;                      // [PADSTRIDE]
    float* wmA = s_s + PADSTRIDE;                      // [4 rows][4 warps]
    float* wmB = wmA + 16;                             // [4 rows][4 warps]

    const int tid  = threadIdx.x;
    const int lane = tid & 31;
    const int w    = tid >> 5;
    const int rib  = w >> 2;          // row in block
    const int h    = w & 3;           // quarter of row
    const long row = (long)blockIdx.x * ROWS_PER_BLOCK + rib;
    float* xr = xs + rib * PADSTRIDE;

    // ---- Stage 1: staging ----
    const float* xrow = x + row * NN;
    #pragma unroll
    for (int i = 0; i < 4; i++) {
        int v4 = h * 128 + i * 32 + lane;
        float4 val = *(const float4*)(xrow + v4 * 4);
        int k = v4 * 4;
        int p = k + (k >> 5);
        xr[p + 0] = val.x;
        xr[p + 1] = val.y;
        xr[p + 2] = val.z;
        xr[p + 3] = val.w;
    }
    // cos/sin tables into padded smem (block-wide, coalesced)
    #pragma unroll
    for (int k = tid; k < NN; k += THREADS) {
        int p = k + (k >> 5);
        c_s[p] = g_cs[k];
        s_s[p] = g_sn[k];
    }
    __syncthreads();

    const int C = h * 32 + lane;       // chunk id 0..127 (fixed per thread)
    const int pbase = 16 * C + (C >> 1);
    const int pnext = 16 * (C + 1) + ((C + 1) >> 1);

    // ---- One-time: chunk tables into registers (conflict-free scalar LDS) ----
    float rc[CHUNK], rs[CHUNK];
    #pragma unroll
    for (int t = 0; t < CHUNK; t++) {
        rc[t] = c_s[pbase + t];
        rs[t] = s_s[pbase + t];
    }
    float Bm = 1.0f;
    #pragma unroll
    for (int t = 0; t < CHUNK; t++) Bm *= -rs[t];

    const float x0 = xr[0];
    // ---- Load chunk x into registers ----
    float xv[CHUNK];
    #pragma unroll
    for (int t = 0; t < CHUNK; t++) xv[t] = xr[pbase + t];
    if (C == 0) {
        // x~[0] = w0 = s_top*x[2047] + c_top*x[0]
        xv[0] = fmaf(s_s[PTOP], xr[PTOP], c_s[PTOP] * x0);
    }

    // ---- Stage 2: chunk affine map (tables from regs) ----
    float A = 0.0f;
    #pragma unroll
    for (int t = CHUNK - 1; t >= 0; t--) {
        A = fmaf(-rs[t], A, rc[t] * xv[t]);
    }

    // ---- Warp suffix scan of affine maps ----
    float gA = A, gB = Bm;
    #pragma unroll
    for (int d = 1; d < 32; d <<= 1) {
        float A2 = __shfl_down_sync(0xffffffffu, gA, d);
        float B2 = __shfl_down_sync(0xffffffffu, gB, d);
        if (lane + d < 32) {
            gA = fmaf(gB, A2, gA);
            gB = gB * B2;
        }
    }
    float nA = __shfl_down_sync(0xffffffffu, gA, 1);
    float nB = __shfl_down_sync(0xffffffffu, gB, 1);
    if (lane == 0) {
        wmA[rib * 4 + h] = gA;
        wmB[rib * 4 + h] = gB;
    }
    __syncthreads();

    // entering carry for this warp = (W_{h+1} o ... o W_3)(x0)
    float cin = x0;
    #pragma unroll
    for (int j = 3; j >= 1; j--) {
        if (j > h) cin = fmaf(wmB[rib * 4 + j], cin, wmA[rib * 4 + j]);
    }
    float carry = (lane == 31) ? cin : fmaf(nB, cin, nA);

    // ---- Stage 3: replay (tables from regs); write y in place ----
    #pragma unroll
    for (int t = CHUNK - 1; t >= 0; t--) {
        float out = fmaf(rc[t], carry, rs[t] * xv[t]);
        carry = fmaf(-rs[t], carry, rc[t] * xv[t]);
        if (t == CHUNK - 1) {
            if (C != 127) xr[pnext] = out;   // y[16(C+1)]
        } else {
            xr[pbase + t + 1] = out;         // y[16C+t+1]
        }
    }
    if (C == 0) xr[0] = carry;               // y[0]
    __syncthreads();

    // ---- Store: padded smem -> coalesced float4 STG ----
    float* yrow = y + row * NN;
    #pragma unroll
    for (int i = 0; i < 4; i++) {
        int v4 = h * 128 + i * 32 + lane;
        int k = v4 * 4;
        int p = k + (k >> 5);
        float4 val;
        val.x = xr[p + 0];
        val.y = xr[p + 1];
        val.z = xr[p + 2];
        val.w = xr[p + 3];
        *(float4*)(yrow + v4 * 4) = val;
    }
}

extern "C" void kernel_launch(void* const* d_in, const int* in_sizes, int n_in,
                              void* d_out, int out_size) {
    const float* x      = (const float*)d_in[0];   // [16384, 2048] fp32
    const float* angles = (const float*)d_in[1];   // [2048] fp32
    float* y = (float*)d_out;                      // [16384, 2048] fp32

    (void)in_sizes; (void)n_in; (void)out_size;

    rg_sincos_kernel<<<(NN + 255) / 256, 256>>>(angles);

    const int smem_bytes = (ROWS_PER_BLOCK * PADSTRIDE + 2 * PADSTRIDE + 32) * sizeof(float);
    static bool attr_set = false;
    if (!attr_set) {
        cudaFuncSetAttribute(rg_givens_kernel,
                             cudaFuncAttributeMaxDynamicSharedMemorySize, smem_bytes);
        attr_set = true;
    }
    rg_givens_kernel<<<NROWS / ROWS_PER_BLOCK, THREADS, smem_bytes>>>(x, y);
}

// round 17
// speedup vs baseline: 1.2170x; 1.0825x over previous
#include <cuda_runtime.h>
#include <cuda_bf16.h>
#include <cstdint>

#define NN 2048
#define NROWS 16384
#define THREADS 256          // 8 warps = 1 row
#define CHUNK 8

__device__ __align__(16) float g_cs[NN];
__device__ __align__(16) float g_sn[NN];

__global__ void rg_sincos_kernel(const float* __restrict__ angles) {
    int k = blockIdx.x * blockDim.x + threadIdx.x;
    if (k < NN) {
        float s, c;
        sincosf(angles[k], &s, &c);
        g_cs[k] = c;
        g_sn[k] = s;
    }
}

// One row per 256-thread block. Lane owns chunk k=8C..8C+7 (= two float4s,
// loaded straight from gmem). Affine map + warp suffix scan + 8-warp smem
// composition; replay in registers; y stored via aligned float4 after a
// one-step shuffle/relay shift. Near-zero smem traffic.
__global__ __launch_bounds__(THREADS)
void rg_givens_kernel(const float* __restrict__ x, float* __restrict__ y) {
    __shared__ float wmA[8], wmB[8], smTop[8], smX[2];

    const int tid  = threadIdx.x;
    const int lane = tid & 31;
    const int h    = tid >> 5;           // warp id 0..7
    const int C    = tid;                // chunk id 0..255
    const long row = blockIdx.x;

    const float4* xr4 = (const float4*)(x + row * NN);
    const float4* c4  = (const float4*)g_cs;
    const float4* s4  = (const float4*)g_sn;

    float4 xa = xr4[2 * C], xb = xr4[2 * C + 1];
    const float4 ca = c4[2 * C], cb = c4[2 * C + 1];
    const float4 sa = s4[2 * C], sb = s4[2 * C + 1];

    if (C == 0)   smX[0] = xa.x;         // x[0]
    if (C == 255) smX[1] = xb.w;         // x[2047]
    __syncthreads();

    const float x0 = smX[0];
    if (C == 0) {
        // x~[0] = w0 = s_2047*x[2047] + c_2047*x[0]
        xa.x = fmaf(g_sn[NN - 1], smX[1], g_cs[NN - 1] * x0);
    }

    // ---- chunk affine map (t = 7..0 descending): carry' = A + B*carry ----
    float A = cb.w * xb.w;            float B = -sb.w;
    A = fmaf(-sb.z, A, cb.z * xb.z);  B *= -sb.z;
    A = fmaf(-sb.y, A, cb.y * xb.y);  B *= -sb.y;
    A = fmaf(-sb.x, A, cb.x * xb.x);  B *= -sb.x;
    A = fmaf(-sa.w, A, ca.w * xa.w);  B *= -sa.w;
    A = fmaf(-sa.z, A, ca.z * xa.z);  B *= -sa.z;
    A = fmaf(-sa.y, A, ca.y * xa.y);  B *= -sa.y;
    A = fmaf(-sa.x, A, ca.x * xa.x);  B *= -sa.x;

    // ---- warp suffix scan of affine maps ----
    float gA = A, gB = B;
    #pragma unroll
    for (int d = 1; d < 32; d <<= 1) {
        float A2 = __shfl_down_sync(0xffffffffu, gA, d);
        float B2 = __shfl_down_sync(0xffffffffu, gB, d);
        if (lane + d < 32) {
            gA = fmaf(gB, A2, gA);
            gB = gB * B2;
        }
    }
    float nA = __shfl_down_sync(0xffffffffu, gA, 1);
    float nB = __shfl_down_sync(0xffffffffu, gB, 1);
    if (lane == 0) {                   // warp total map
        wmA[h] = gA;
        wmB[h] = gB;
    }
    __syncthreads();

    // carry entering this warp = (W_{h+1} o ... o W_7)(x0)
    float cin = x0;
    #pragma unroll
    for (int j = 7; j >= 1; j--) {
        if (j > h) cin = fmaf(wmB[j], cin, wmA[j]);
    }
    float carry = (lane == 31) ? cin : fmaf(nB, cin, nA);

    // ---- replay (t = 7..0): out_t = y[8C+t+1] ----
    float o7 = fmaf(cb.w, carry, sb.w * xb.w); carry = fmaf(-sb.w, carry, cb.w * xb.w);
    float o6 = fmaf(cb.z, carry, sb.z * xb.z); carry = fmaf(-sb.z, carry, cb.z * xb.z);
    float o5 = fmaf(cb.y, carry, sb.y * xb.y); carry = fmaf(-sb.y, carry, cb.y * xb.y);
    float o4 = fmaf(cb.x, carry, sb.x * xb.x); carry = fmaf(-sb.x, carry, cb.x * xb.x);
    float o3 = fmaf(ca.w, carry, sa.w * xa.w); carry = fmaf(-sa.w, carry, ca.w * xa.w);
    float o2 = fmaf(ca.z, carry, sa.z * xa.z); carry = fmaf(-sa.z, carry, ca.z * xa.z);
    float o1 = fmaf(ca.y, carry, sa.y * xa.y); carry = fmaf(-sa.y, carry, ca.y * xa.y);
    float o0 = fmaf(ca.x, carry, sa.x * xa.x); carry = fmaf(-sa.x, carry, ca.x * xa.x);

    // ---- shift: slot y[8C] comes from chunk C-1's o7 (= y[8(C-1)+8]) ----
    float up = __shfl_up_sync(0xffffffffu, o7, 1);
    if (lane == 31) smTop[h] = o7;     // relay for next warp's lane 0
    __syncthreads();

    float recv;
    if (lane == 0) {
        recv = (h == 0) ? carry        // y[0] = exit carry of the whole chain
                        : smTop[h - 1];
    } else {
        recv = up;
    }

    // ---- aligned coalesced-ish stores (sectors fully consumed) ----
    float4* yr4 = (float4*)(y + row * NN);
    yr4[2 * C]     = make_float4(recv, o0, o1, o2);
    yr4[2 * C + 1] = make_float4(o3, o4, o5, o6);
}

extern "C" void kernel_launch(void* const* d_in, const int* in_sizes, int n_in,
                              void* d_out, int out_size) {
    const float* x      = (const float*)d_in[0];   // [16384, 2048] fp32
    const float* angles = (const float*)d_in[1];   // [2048] fp32
    float* y = (float*)d_out;                      // [16384, 2048] fp32

    (void)in_sizes; (void)n_in; (void)out_size;

    rg_sincos_kernel<<<(NN + 255) / 256, 256>>>(angles);
    rg_givens_kernel<<<NROWS, THREADS>>>(x, y);
}